// round 1
// baseline (speedup 1.0000x reference)
#include <cuda_runtime.h>
#include <math.h>
#include <stdint.h>

// GCN: 4 layers over N=100000 nodes, E=3200000 edges.
// Strategy: CSR-by-col build once per launch, warp-per-node aggregation,
// aggregate-then-GEMM on the cheap side (8 feats layer1, 1 feat output).

#define NMAX 100000
#define EMAX 3200000

// ---------------- scratch (static __device__, no allocations) ----------------
__device__ int   g_is64;
__device__ int   g_row[EMAX];
__device__ int   g_col[EMAX];
__device__ float g_w[EMAX];
__device__ float g_degw[NMAX];
__device__ float g_dinvw[NMAX];
__device__ float g_dinv1[NMAX];
__device__ int   g_cnt[NMAX];
__device__ int   g_indptr[NMAX + 1];
__device__ int   g_cursor[NMAX];
__device__ int2  g_mw[EMAX];   // {row, __float_as_int(norm_weighted)}
__device__ int2  g_m1[EMAX];   // {row, __float_as_int(norm_ones)}
__device__ float g_h0[NMAX * 8];
__device__ float g_agg8[NMAX * 8];
__device__ float g_A[NMAX * 64];
__device__ float g_B[NMAX * 64];
__device__ float g_s[NMAX];

// ---------------- helpers ----------------
__device__ __forceinline__ float softplus_f(float x) {
    return fmaxf(x, 0.f) + log1pf(expf(-fabsf(x)));
}

__device__ __forceinline__ float warp_sum(float v) {
    #pragma unroll
    for (int off = 16; off > 0; off >>= 1)
        v += __shfl_down_sync(0xFFFFFFFFu, v, off);
    return v;
}

// ---------------- kernels ----------------

// Detect whether edge_index buffer is int64 (odd 32-bit words all zero) or int32.
__global__ void k_detect(const int* __restrict__ p) {
    __shared__ int zc;
    if (threadIdx.x == 0) zc = 0;
    __syncthreads();
    int local = 0;
    for (int i = threadIdx.x; i < 1024; i += blockDim.x)
        if (p[2 * i + 1] == 0) local++;
    atomicAdd(&zc, local);
    __syncthreads();
    if (threadIdx.x == 0) g_is64 = (zc > 1000) ? 1 : 0;
}

__global__ void k_init(int n) {
    int i = blockIdx.x * blockDim.x + threadIdx.x;
    if (i < n) {
        g_degw[i] = 1.0f;   // self-loop weight
        g_cnt[i] = 0;
    }
}

// Convert indices, compute edge weight, histogram in-degree.
__global__ void k_convert(const void* __restrict__ idx,
                          const float* __restrict__ dist, int E) {
    int e = blockIdx.x * blockDim.x + threadIdx.x;
    if (e >= E) return;
    int r, c;
    if (g_is64) {
        const long long* p = (const long long*)idx;
        r = (int)p[e];
        c = (int)p[e + E];
    } else {
        const int* p = (const int*)idx;
        r = p[e];
        c = p[e + E];
    }
    float w = 1.0f / (dist[e] + 1e-6f);
    g_row[e] = r;
    g_col[e] = c;
    g_w[e] = w;
    atomicAdd(&g_degw[c], w);
    atomicAdd(&g_cnt[c], 1);
}

__global__ void k_dinv(int n) {
    int i = blockIdx.x * blockDim.x + threadIdx.x;
    if (i < n) {
        g_dinvw[i] = rsqrtf(g_degw[i]);            // degw >= 1 always
        g_dinv1[i] = rsqrtf((float)g_cnt[i] + 1.f); // >= 1 always
    }
}

// Single-block exclusive scan of g_cnt -> g_indptr, also fills g_cursor.
__global__ void k_scan(int n) {
    __shared__ int part[1024];
    int t = threadIdx.x;
    int chunk = (n + 1023) / 1024;
    int lo = t * chunk;
    int hi = min(lo + chunk, n);
    int s = 0;
    for (int i = lo; i < hi; i++) s += g_cnt[i];
    part[t] = s;
    __syncthreads();
    // inclusive Hillis-Steele scan
    for (int off = 1; off < 1024; off <<= 1) {
        int v = (t >= off) ? part[t - off] : 0;
        __syncthreads();
        part[t] += v;
        __syncthreads();
    }
    int run = part[t] - s;   // exclusive prefix
    for (int i = lo; i < hi; i++) {
        g_indptr[i] = run;
        g_cursor[i] = run;
        run += g_cnt[i];
    }
    if (t == 1023) g_indptr[n] = run;   // == E
}

// Place edges into CSR order with precomputed norms.
__global__ void k_place(int E) {
    int e = blockIdx.x * blockDim.x + threadIdx.x;
    if (e >= E) return;
    int r = g_row[e];
    int c = g_col[e];
    int pos = atomicAdd(&g_cursor[c], 1);
    float nw = g_dinvw[r] * g_w[e] * g_dinvw[c];
    float n1 = g_dinv1[r] * g_dinv1[c];
    g_mw[pos] = make_int2(r, __float_as_int(nw));
    g_m1[pos] = make_int2(r, __float_as_int(n1));
}

// Build H0 = concat of 8 node features.
__global__ void k_h0(const float* __restrict__ x,
                     const float* __restrict__ dtr,
                     const float* __restrict__ npd,
                     const float* __restrict__ kp,
                     const float* __restrict__ kpp,
                     const float* __restrict__ imin,
                     const float* __restrict__ imax, int n) {
    int i = blockIdx.x * blockDim.x + threadIdx.x;
    if (i >= n) return;
    float4 a = make_float4(x[2 * i], x[2 * i + 1], dtr[i], npd[i]);
    float4 b = make_float4(kp[i], kpp[i], imin[i], imax[i]);
    ((float4*)g_h0)[2 * i] = a;
    ((float4*)g_h0)[2 * i + 1] = b;
}

// Aggregate 8-feature H0 with weighted norms. Warp per node; lanes mirror f=lane&7.
__global__ void k_agg8(int n) {
    int w = (blockIdx.x * blockDim.x + threadIdx.x) >> 5;
    if (w >= n) return;
    int lane = threadIdx.x & 31;
    int f = lane & 7;
    float dv = g_dinvw[w];
    float acc = dv * dv * g_h0[w * 8 + f];
    int e = g_indptr[w], end = g_indptr[w + 1];
    for (; e < end; e++) {
        int2 m = g_mw[e];
        acc += __int_as_float(m.y) * g_h0[m.x * 8 + f];
    }
    if (lane < 8) g_agg8[w * 8 + f] = acc;
}

// Aggregate 64-feature tensor with weighted norms. Warp per node, 2 feats/lane.
__global__ void k_agg64(const float* __restrict__ h, float* __restrict__ agg, int n) {
    int w = (blockIdx.x * blockDim.x + threadIdx.x) >> 5;
    if (w >= n) return;
    int lane = threadIdx.x & 31;
    float dv = g_dinvw[w];
    float c0 = dv * dv;
    const float* hr = h + (size_t)w * 64;
    float a0 = c0 * hr[lane];
    float a1 = c0 * hr[lane + 32];
    int e = g_indptr[w], end = g_indptr[w + 1];
    for (; e < end; e++) {
        int2 m = g_mw[e];
        float coef = __int_as_float(m.y);
        const float* src = h + (size_t)m.x * 64;
        a0 += coef * src[lane];
        a1 += coef * src[lane + 32];
    }
    agg[(size_t)w * 64 + lane] = a0;
    agg[(size_t)w * 64 + lane + 32] = a1;
}

// GEMM [n,F] x [F,64] + bias, optional softplus. W columns live in registers.
template <int F>
__global__ void k_gemm(const float* __restrict__ in, const float* __restrict__ W,
                       const float* __restrict__ b, float* __restrict__ out, int n) {
    __shared__ float sIn[4 * F];
    int o = threadIdx.x & 63;
    int nl = threadIdx.x >> 6;   // 0..3
    float wreg[F];
    #pragma unroll
    for (int f = 0; f < F; f++) wreg[f] = W[f * 64 + o];
    float bias = b[o];
    int base = blockIdx.x * 128;
    for (int k = 0; k < 128; k += 4) {
        __syncthreads();
        for (int i = threadIdx.x; i < 4 * F; i += 256) {
            int node = base + k + i / F;
            sIn[i] = (node < n) ? in[(size_t)node * F + (i % F)] : 0.f;
        }
        __syncthreads();
        int node = base + k + nl;
        if (node < n) {
            float acc = bias;
            #pragma unroll
            for (int f = 0; f < F; f++) acc += sIn[nl * F + f] * wreg[f];
            out[(size_t)node * 64 + o] = softplus_f(acc);
        }
    }
}

// s[n] = h3[n,:] . Wout[:,0]   (warp per node)
__global__ void k_wout(const float* __restrict__ h, const float* __restrict__ Wout, int n) {
    int w = (blockIdx.x * blockDim.x + threadIdx.x) >> 5;
    if (w >= n) return;
    int lane = threadIdx.x & 31;
    const float* hr = h + (size_t)w * 64;
    float v = hr[lane] * Wout[lane] + hr[lane + 32] * Wout[lane + 32];
    v = warp_sum(v);
    if (lane == 0) g_s[w] = v;
}

// out[n] = bout + dinv1[n]^2 * s[n] + sum_e n1[e]*s[row[e]]  (warp per node)
__global__ void k_out(const float* __restrict__ bout, float* __restrict__ out, int n) {
    int w = (blockIdx.x * blockDim.x + threadIdx.x) >> 5;
    if (w >= n) return;
    int lane = threadIdx.x & 31;
    int beg = g_indptr[w], end = g_indptr[w + 1];
    float acc = 0.f;
    for (int e = beg + lane; e < end; e += 32) {
        int2 m = g_m1[e];
        acc += __int_as_float(m.y) * g_s[m.x];
    }
    acc = warp_sum(acc);
    if (lane == 0) {
        float dv = g_dinv1[w];
        out[w] = acc + dv * dv * g_s[w] + bout[0];
    }
}

// ---------------- launch ----------------
extern "C" void kernel_launch(void* const* d_in, const int* in_sizes, int n_in,
                              void* d_out, int out_size) {
    (void)n_in;
    const void*  edge_idx = d_in[8];
    const float* edge_d   = (const float*)d_in[9];
    const float* x    = (const float*)d_in[1];
    const float* dtr  = (const float*)d_in[2];
    const float* npd  = (const float*)d_in[3];
    const float* kp   = (const float*)d_in[4];
    const float* kpp  = (const float*)d_in[5];
    const float* imin = (const float*)d_in[6];
    const float* imax = (const float*)d_in[7];
    const float* W1 = (const float*)d_in[10];
    const float* b1 = (const float*)d_in[11];
    const float* W2 = (const float*)d_in[12];
    const float* b2 = (const float*)d_in[13];
    const float* W3 = (const float*)d_in[14];
    const float* b3 = (const float*)d_in[15];
    const float* Wout = (const float*)d_in[16];
    const float* bout = (const float*)d_in[17];

    int N = in_sizes[1] / 2;          // x is [N,2]
    int E = in_sizes[9];              // edge_distance is [E]
    if (N > NMAX) N = NMAX;
    if (E > EMAX) E = EMAX;
    (void)out_size;

    float *pA = nullptr, *pB = nullptr, *pAgg8 = nullptr;
    cudaGetSymbolAddress((void**)&pA, g_A);
    cudaGetSymbolAddress((void**)&pB, g_B);
    cudaGetSymbolAddress((void**)&pAgg8, g_agg8);

    const int T = 256;
    int gN  = (N + T - 1) / T;
    int gE  = (E + T - 1) / T;
    int gW  = (N * 32 + T - 1) / T;       // warp-per-node kernels
    int gG  = (N + 127) / 128;            // gemm blocks

    k_detect<<<1, 256>>>((const int*)edge_idx);
    k_init<<<gN, T>>>(N);
    k_convert<<<gE, T>>>(edge_idx, edge_d, E);
    k_dinv<<<gN, T>>>(N);
    k_scan<<<1, 1024>>>(N);
    k_place<<<gE, T>>>(E);
    k_h0<<<gN, T>>>(x, dtr, npd, kp, kpp, imin, imax, N);

    // Layer 1: aggregate 8 feats, then GEMM(8->64)+softplus
    k_agg8<<<gW, T>>>(N);
    k_gemm<8><<<gG, 256>>>(pAgg8, W1, b1, pA, N);

    // Layer 2
    k_agg64<<<gW, T>>>(pA, pB, N);
    k_gemm<64><<<gG, 256>>>(pB, W2, b2, pA, N);

    // Layer 3
    k_agg64<<<gW, T>>>(pA, pB, N);
    k_gemm<64><<<gG, 256>>>(pB, W3, b3, pA, N);

    // Output conv: project to scalar first, then aggregate with ones-norms
    k_wout<<<gW, T>>>(pA, Wout, N);
    k_out<<<gW, T>>>(bout, (float*)d_out, N);
}

// round 2
// speedup vs baseline: 1.1503x; 1.1503x over previous
#include <cuda_runtime.h>
#include <math.h>
#include <stdint.h>

// GCN: 4 layers over N=100000 nodes, E=3200000 edges.
// CSR-by-col build per launch (no cached state), warp-per-node aggregation with
// vectorized gathers, aggregate-then-GEMM on the cheap side (8 feats layer1,
// scalar for the output conv).

#define NMAX 100000
#define EMAX 3200000

// ---------------- scratch (static __device__, no allocations) ----------------
__device__ int   g_is64;
__device__ float g_degw[NMAX];
__device__ int   g_cnt[NMAX];
__device__ float g_dinvw[NMAX];
__device__ float g_dinv1[NMAX];
__device__ int   g_indptr[NMAX + 1];
__device__ int   g_cursor[NMAX];
__device__ int2  g_mw[EMAX];        // {row, __float_as_int(dinvw[row]*w)}
__device__ float g_h0[NMAX * 8];
__device__ float g_agg8[NMAX * 8];
__device__ float g_A[NMAX * 64];
__device__ float g_B[NMAX * 64];
__device__ float g_s1[NMAX];        // dinv1[n] * (h3[n] . Wout)

// ---------------- helpers ----------------
__device__ __forceinline__ float softplus_f(float x) {
    return fmaxf(x, 0.f) + log1pf(expf(-fabsf(x)));
}

__device__ __forceinline__ float warp_sum(float v) {
    #pragma unroll
    for (int off = 16; off > 0; off >>= 1)
        v += __shfl_down_sync(0xFFFFFFFFu, v, off);
    return v;
}

__device__ __forceinline__ void decode_edge(const void* idx, int E, int e,
                                            int& r, int& c) {
    if (g_is64) {
        const long long* p = (const long long*)idx;
        r = (int)p[e];
        c = (int)p[e + E];
    } else {
        const int* p = (const int*)idx;
        r = p[e];
        c = p[e + E];
    }
}

// ---------------- kernels ----------------

// Detect whether edge_index buffer is int64 (odd 32-bit words ~all zero) or int32.
__global__ void k_detect(const int* __restrict__ p) {
    __shared__ int zc;
    if (threadIdx.x == 0) zc = 0;
    __syncthreads();
    int local = 0;
    for (int i = threadIdx.x; i < 1024; i += blockDim.x)
        if (p[2 * i + 1] == 0) local++;
    atomicAdd(&zc, local);
    __syncthreads();
    if (threadIdx.x == 0) g_is64 = (zc > 1000) ? 1 : 0;
}

__global__ void k_init(int n) {
    int i = blockIdx.x * blockDim.x + threadIdx.x;
    if (i < n) {
        g_degw[i] = 1.0f;   // self-loop weight
        g_cnt[i] = 0;
    }
}

// Pass 1: histogram weighted/unweighted in-degree (only needs col + weight).
__global__ void k_convert(const void* __restrict__ idx,
                          const float* __restrict__ dist, int E) {
    int e = blockIdx.x * blockDim.x + threadIdx.x;
    if (e >= E) return;
    int c;
    if (g_is64) c = (int)((const long long*)idx)[e + E];
    else        c = ((const int*)idx)[e + E];
    float w = 1.0f / (dist[e] + 1e-6f);
    atomicAdd(&g_degw[c], w);
    atomicAdd(&g_cnt[c], 1);
}

__global__ void k_dinv(int n) {
    int i = blockIdx.x * blockDim.x + threadIdx.x;
    if (i < n) {
        g_dinvw[i] = rsqrtf(g_degw[i]);             // degw >= 1 always
        g_dinv1[i] = rsqrtf((float)g_cnt[i] + 1.f); // >= 1 always
    }
}

// Single-block exclusive scan of g_cnt -> g_indptr, also fills g_cursor.
__global__ void k_scan(int n) {
    __shared__ int part[1024];
    int t = threadIdx.x;
    int chunk = (n + 1023) / 1024;
    int lo = t * chunk;
    int hi = min(lo + chunk, n);
    int s = 0;
    for (int i = lo; i < hi; i++) s += g_cnt[i];
    part[t] = s;
    __syncthreads();
    for (int off = 1; off < 1024; off <<= 1) {
        int v = (t >= off) ? part[t - off] : 0;
        __syncthreads();
        part[t] += v;
        __syncthreads();
    }
    int run = part[t] - s;   // exclusive prefix
    for (int i = lo; i < hi; i++) {
        g_indptr[i] = run;
        g_cursor[i] = run;
        run += g_cnt[i];
    }
    if (t == 1023) g_indptr[n] = run;   // == E
}

// Pass 2: place edges into CSR order with precomputed source-side coefficient.
// Full norm for edge (r->c) is dinvw[r]*w*dinvw[c]; dinvw[c] is factored out
// and applied once per node in the aggregation kernels.
__global__ void k_place(const void* __restrict__ idx,
                        const float* __restrict__ dist, int E) {
    int e = blockIdx.x * blockDim.x + threadIdx.x;
    if (e >= E) return;
    int r, c;
    decode_edge(idx, E, e, r, c);
    float w = 1.0f / (dist[e] + 1e-6f);
    int pos = atomicAdd(&g_cursor[c], 1);
    g_mw[pos] = make_int2(r, __float_as_int(g_dinvw[r] * w));
}

// Build H0 = concat of 8 node features.
__global__ void k_h0(const float* __restrict__ x,
                     const float* __restrict__ dtr,
                     const float* __restrict__ npd,
                     const float* __restrict__ kp,
                     const float* __restrict__ kpp,
                     const float* __restrict__ imin,
                     const float* __restrict__ imax, int n) {
    int i = blockIdx.x * blockDim.x + threadIdx.x;
    if (i >= n) return;
    float4 a = make_float4(x[2 * i], x[2 * i + 1], dtr[i], npd[i]);
    float4 b = make_float4(kp[i], kpp[i], imin[i], imax[i]);
    ((float4*)g_h0)[2 * i] = a;
    ((float4*)g_h0)[2 * i + 1] = b;
}

// Aggregate 8-feature H0. Warp per node, 4 edges per iteration:
// lane group g = lane>>3 handles edge e0+g, feature f = lane&7.
__global__ void k_agg8(int n) {
    int w = (blockIdx.x * blockDim.x + threadIdx.x) >> 5;
    if (w >= n) return;
    int lane = threadIdx.x & 31;
    int g = lane >> 3;
    int f = lane & 7;
    int beg = g_indptr[w], end = g_indptr[w + 1];
    float acc = 0.f;
    for (int e0 = beg; e0 < end; e0 += 4) {
        int e = e0 + g;
        if (e < end) {
            int2 m = __ldg(&g_mw[e]);
            acc += __int_as_float(m.y) * g_h0[m.x * 8 + f];
        }
    }
    acc += __shfl_xor_sync(0xFFFFFFFFu, acc, 8);
    acc += __shfl_xor_sync(0xFFFFFFFFu, acc, 16);
    if (lane < 8) {
        float dv = g_dinvw[w];
        g_agg8[w * 8 + f] = dv * (acc + dv * g_h0[w * 8 + f]);
    }
}

// Aggregate 64-feature tensor. Warp per node, 2 edges per iteration:
// half = lane>>4 selects the edge, 16 lanes x float4 cover the 64 features.
__global__ void k_agg64(const float* __restrict__ h, float* __restrict__ agg, int n) {
    int w = (blockIdx.x * blockDim.x + threadIdx.x) >> 5;
    if (w >= n) return;
    int lane = threadIdx.x & 31;
    int half = lane >> 4;
    int l16 = lane & 15;
    int beg = g_indptr[w], end = g_indptr[w + 1];
    float4 acc = make_float4(0.f, 0.f, 0.f, 0.f);
    for (int e = beg; e < end; e += 2) {
        int ee = e + half;
        float vr = 0.f;
        int r = w;
        if (ee < end) {
            int2 m = __ldg(&g_mw[ee]);
            r = m.x;
            vr = __int_as_float(m.y);
        }
        float4 v = __ldg((const float4*)(h + (size_t)r * 64) + l16);
        acc.x = fmaf(vr, v.x, acc.x);
        acc.y = fmaf(vr, v.y, acc.y);
        acc.z = fmaf(vr, v.z, acc.z);
        acc.w = fmaf(vr, v.w, acc.w);
    }
    acc.x += __shfl_down_sync(0xFFFFFFFFu, acc.x, 16);
    acc.y += __shfl_down_sync(0xFFFFFFFFu, acc.y, 16);
    acc.z += __shfl_down_sync(0xFFFFFFFFu, acc.z, 16);
    acc.w += __shfl_down_sync(0xFFFFFFFFu, acc.w, 16);
    if (half == 0) {
        float dv = g_dinvw[w];
        float4 sv = __ldg((const float4*)(h + (size_t)w * 64) + l16);
        float4 o;
        o.x = dv * (acc.x + dv * sv.x);
        o.y = dv * (acc.y + dv * sv.y);
        o.z = dv * (acc.z + dv * sv.z);
        o.w = dv * (acc.w + dv * sv.w);
        ((float4*)(agg + (size_t)w * 64))[l16] = o;
    }
}

// GEMM [n,F] x [F,64] + bias + softplus. W columns live in registers.
template <int F>
__global__ void k_gemm(const float* __restrict__ in, const float* __restrict__ W,
                       const float* __restrict__ b, float* __restrict__ out, int n) {
    __shared__ float sIn[4 * F];
    int o = threadIdx.x & 63;
    int nl = threadIdx.x >> 6;   // 0..3
    float wreg[F];
    #pragma unroll
    for (int f = 0; f < F; f++) wreg[f] = W[f * 64 + o];
    float bias = b[o];
    int base = blockIdx.x * 128;
    for (int k = 0; k < 128; k += 4) {
        __syncthreads();
        for (int i = threadIdx.x; i < 4 * F; i += 256) {
            int node = base + k + i / F;
            sIn[i] = (node < n) ? in[(size_t)node * F + (i % F)] : 0.f;
        }
        __syncthreads();
        int node = base + k + nl;
        if (node < n) {
            float acc = bias;
            #pragma unroll
            for (int f = 0; f < F; f++) acc = fmaf(sIn[nl * F + f], wreg[f], acc);
            out[(size_t)node * 64 + o] = softplus_f(acc);
        }
    }
}

// s1[n] = dinv1[n] * (h3[n,:] . Wout[:,0])   (warp per node)
__global__ void k_wout(const float* __restrict__ h, const float* __restrict__ Wout, int n) {
    int w = (blockIdx.x * blockDim.x + threadIdx.x) >> 5;
    if (w >= n) return;
    int lane = threadIdx.x & 31;
    const float* hr = h + (size_t)w * 64;
    float v = hr[lane] * Wout[lane] + hr[lane + 32] * Wout[lane + 32];
    v = warp_sum(v);
    if (lane == 0) g_s1[w] = g_dinv1[w] * v;
}

// out[n] = bout + dinv1[n] * (s1[n] + sum_e s1[row[e]])   (warp per node)
__global__ void k_out(const float* __restrict__ bout, float* __restrict__ out, int n) {
    int w = (blockIdx.x * blockDim.x + threadIdx.x) >> 5;
    if (w >= n) return;
    int lane = threadIdx.x & 31;
    int beg = g_indptr[w], end = g_indptr[w + 1];
    float acc = 0.f;
    for (int e = beg + lane; e < end; e += 32) {
        int r = __ldg(&g_mw[e]).x;
        acc += g_s1[r];
    }
    acc = warp_sum(acc);
    if (lane == 0)
        out[w] = bout[0] + g_dinv1[w] * (acc + g_s1[w]);
}

// ---------------- launch ----------------
extern "C" void kernel_launch(void* const* d_in, const int* in_sizes, int n_in,
                              void* d_out, int out_size) {
    (void)n_in; (void)out_size;
    const void*  edge_idx = d_in[8];
    const float* edge_d   = (const float*)d_in[9];
    const float* x    = (const float*)d_in[1];
    const float* dtr  = (const float*)d_in[2];
    const float* npd  = (const float*)d_in[3];
    const float* kp   = (const float*)d_in[4];
    const float* kpp  = (const float*)d_in[5];
    const float* imin = (const float*)d_in[6];
    const float* imax = (const float*)d_in[7];
    const float* W1 = (const float*)d_in[10];
    const float* b1 = (const float*)d_in[11];
    const float* W2 = (const float*)d_in[12];
    const float* b2 = (const float*)d_in[13];
    const float* W3 = (const float*)d_in[14];
    const float* b3 = (const float*)d_in[15];
    const float* Wout = (const float*)d_in[16];
    const float* bout = (const float*)d_in[17];

    int N = in_sizes[1] / 2;          // x is [N,2]
    int E = in_sizes[9];              // edge_distance is [E]
    if (N > NMAX) N = NMAX;
    if (E > EMAX) E = EMAX;

    float *pA = nullptr, *pB = nullptr, *pAgg8 = nullptr;
    cudaGetSymbolAddress((void**)&pA, g_A);
    cudaGetSymbolAddress((void**)&pB, g_B);
    cudaGetSymbolAddress((void**)&pAgg8, g_agg8);

    const int T = 256;
    int gN  = (N + T - 1) / T;
    int gE  = (E + T - 1) / T;
    int gW  = (N * 32 + T - 1) / T;       // warp-per-node kernels
    int gG  = (N + 127) / 128;            // gemm blocks

    k_detect<<<1, 256>>>((const int*)edge_idx);
    k_init<<<gN, T>>>(N);
    k_convert<<<gE, T>>>(edge_idx, edge_d, E);
    k_dinv<<<gN, T>>>(N);
    k_scan<<<1, 1024>>>(N);
    k_place<<<gE, T>>>(edge_idx, edge_d, E);
    k_h0<<<gN, T>>>(x, dtr, npd, kp, kpp, imin, imax, N);

    // Layer 1: aggregate 8 feats, then GEMM(8->64)+softplus
    k_agg8<<<gW, T>>>(N);
    k_gemm<8><<<gG, 256>>>(pAgg8, W1, b1, pA, N);

    // Layer 2
    k_agg64<<<gW, T>>>(pA, pB, N);
    k_gemm<64><<<gG, 256>>>(pB, W2, b2, pA, N);

    // Layer 3
    k_agg64<<<gW, T>>>(pA, pB, N);
    k_gemm<64><<<gG, 256>>>(pB, W3, b3, pA, N);

    // Output conv: project to scalar first, then aggregate with ones-norms
    k_wout<<<gW, T>>>(pA, Wout, N);
    k_out<<<gW, T>>>(bout, (float*)d_out, N);
}

// round 3
// speedup vs baseline: 1.5242x; 1.3250x over previous
#include <cuda_runtime.h>
#include <math.h>
#include <stdint.h>

// GCN: 4 layers over N=100000 nodes, E=3200000 edges.
// CSR-by-col build per launch, warp-per-node aggregation with vectorized
// gathers, aggregate-then-GEMM on the cheap side (8 feats layer1, scalar for
// the output conv, whose projection is fused into the layer-3 GEMM).

#define NMAX 100000
#define EMAX 3200000
#define NB_SCAN ((NMAX + 1023) / 1024)

// ---------------- scratch (static __device__, no allocations) ----------------
__device__ int   g_is64;
__device__ float g_degw[NMAX];
__device__ int   g_cnt[NMAX + 4];
__device__ float g_dinvw[NMAX];
__device__ float g_dinv1[NMAX];
__device__ int   g_indptr[NMAX + 1];
__device__ int   g_cursor[NMAX];
__device__ int   g_bsum[256];
__device__ int   g_boff[256];
__device__ int2  g_mw[EMAX];        // {row, __float_as_int(dinvw[row]*w)}
__device__ float g_h0[NMAX * 8];
__device__ float g_agg8[NMAX * 8];
__device__ float g_A[NMAX * 64];
__device__ float g_B[NMAX * 64];
__device__ float g_s1[NMAX];        // dinv1[n] * (h3[n] . Wout)

// ---------------- helpers ----------------
__device__ __forceinline__ float softplus_f(float x) {
    return fmaxf(x, 0.f) + log1pf(expf(-fabsf(x)));
}

__device__ __forceinline__ float warp_sum(float v) {
    #pragma unroll
    for (int off = 16; off > 0; off >>= 1)
        v += __shfl_down_sync(0xFFFFFFFFu, v, off);
    return v;
}

// ---------------- kernels ----------------

// Init degree arrays; block 0 additionally detects int64 vs int32 edge_index.
__global__ void k_init_detect(const int* __restrict__ p, int n) {
    int i = blockIdx.x * blockDim.x + threadIdx.x;
    if (i < n) {
        g_degw[i] = 1.0f;   // self-loop weight
        g_cnt[i] = 0;
    }
    if (blockIdx.x == 0) {
        __shared__ int zc;
        if (threadIdx.x == 0) zc = 0;
        __syncthreads();
        int local = 0;
        for (int j = threadIdx.x; j < 1024; j += blockDim.x)
            if (p[2 * j + 1] == 0) local++;
        atomicAdd(&zc, local);
        __syncthreads();
        if (threadIdx.x == 0) g_is64 = (zc > 1000) ? 1 : 0;
    }
}

// Pass 1: histogram weighted/unweighted in-degree (only needs col + weight).
__global__ void k_convert(const void* __restrict__ idx,
                          const float* __restrict__ dist, int E) {
    int e = blockIdx.x * blockDim.x + threadIdx.x;
    if (e >= E) return;
    int c;
    if (g_is64) c = (int)((const long long*)idx)[e + E];
    else        c = ((const int*)idx)[e + E];
    float w = 1.0f / (dist[e] + 1e-6f);
    atomicAdd(&g_degw[c], w);
    atomicAdd(&g_cnt[c], 1);
}

// Scan stage A: per-block sums of g_cnt (1024 counts per block, coalesced).
__global__ void k_bsum(int n) {
    int t = threadIdx.x;
    int i0 = blockIdx.x * 1024 + t * 4;
    int s = 0;
    if (i0 + 3 < n) {
        int4 v = *(const int4*)&g_cnt[i0];
        s = v.x + v.y + v.z + v.w;
    } else {
        #pragma unroll
        for (int j = 0; j < 4; j++) { int i = i0 + j; if (i < n) s += g_cnt[i]; }
    }
    #pragma unroll
    for (int off = 16; off > 0; off >>= 1)
        s += __shfl_down_sync(0xFFFFFFFFu, s, off);
    __shared__ int ws[8];
    if ((t & 31) == 0) ws[t >> 5] = s;
    __syncthreads();
    if (t == 0) {
        int tot = 0;
        #pragma unroll
        for (int k = 0; k < 8; k++) tot += ws[k];
        g_bsum[blockIdx.x] = tot;
    }
}

// Scan stage B: exclusive scan of the (<=128) block sums.
__global__ void k_bscan(int nb, int n) {
    __shared__ int sh[128];
    int t = threadIdx.x;
    int v = (t < nb) ? g_bsum[t] : 0;
    sh[t] = v;
    __syncthreads();
    for (int off = 1; off < 128; off <<= 1) {
        int u = (t >= off) ? sh[t - off] : 0;
        __syncthreads();
        sh[t] += u;
        __syncthreads();
    }
    if (t < nb) g_boff[t] = sh[t] - v;     // exclusive prefix
    if (t == nb - 1) g_indptr[n] = sh[t];  // == E
}

// Scan stage C + fused per-node work: write indptr/cursor, dinvw/dinv1, H0.
__global__ void k_fill(const float* __restrict__ x,
                       const float* __restrict__ dtr,
                       const float* __restrict__ npd,
                       const float* __restrict__ kp,
                       const float* __restrict__ kpp,
                       const float* __restrict__ imin,
                       const float* __restrict__ imax, int n) {
    int t = threadIdx.x;
    int lane = t & 31;
    int warp = t >> 5;
    int i0 = blockIdx.x * 1024 + t * 4;

    int c[4];
    #pragma unroll
    for (int j = 0; j < 4; j++) {
        int i = i0 + j;
        c[j] = (i < n) ? g_cnt[i] : 0;
    }
    int tsum = c[0] + c[1] + c[2] + c[3];

    // warp-inclusive scan of per-thread sums
    int inc = tsum;
    #pragma unroll
    for (int off = 1; off < 32; off <<= 1) {
        int u = __shfl_up_sync(0xFFFFFFFFu, inc, off);
        if (lane >= off) inc += u;
    }
    __shared__ int wsum[8];
    if (lane == 31) wsum[warp] = inc;
    __syncthreads();
    int woff = 0;
    for (int k = 0; k < warp; k++) woff += wsum[k];

    int excl = g_boff[blockIdx.x] + woff + (inc - tsum);
    #pragma unroll
    for (int j = 0; j < 4; j++) {
        int i = i0 + j;
        if (i < n) {
            g_indptr[i] = excl;
            g_cursor[i] = excl;
            g_dinvw[i] = rsqrtf(g_degw[i]);
            g_dinv1[i] = rsqrtf((float)c[j] + 1.f);
            float2 xv = ((const float2*)x)[i];
            float4 a = make_float4(xv.x, xv.y, dtr[i], npd[i]);
            float4 b = make_float4(kp[i], kpp[i], imin[i], imax[i]);
            ((float4*)g_h0)[2 * i] = a;
            ((float4*)g_h0)[2 * i + 1] = b;
            excl += c[j];
        }
    }
}

// Pass 2: place edges into CSR order with precomputed source-side coefficient.
// Full norm for (r->c) is dinvw[r]*w*dinvw[c]; dinvw[c] is applied per node
// in the aggregation kernels.
__global__ void k_place(const void* __restrict__ idx,
                        const float* __restrict__ dist, int E) {
    int e = blockIdx.x * blockDim.x + threadIdx.x;
    if (e >= E) return;
    int r, c;
    if (g_is64) {
        const long long* p = (const long long*)idx;
        r = (int)p[e];
        c = (int)p[e + E];
    } else {
        const int* p = (const int*)idx;
        r = p[e];
        c = p[e + E];
    }
    float w = 1.0f / (dist[e] + 1e-6f);
    int pos = atomicAdd(&g_cursor[c], 1);
    g_mw[pos] = make_int2(r, __float_as_int(g_dinvw[r] * w));
}

// Aggregate 8-feature H0. Warp per node, 4 edges per iteration:
// lane group g = lane>>3 handles edge e0+g, feature f = lane&7.
__global__ void k_agg8(int n) {
    int w = (blockIdx.x * blockDim.x + threadIdx.x) >> 5;
    if (w >= n) return;
    int lane = threadIdx.x & 31;
    int g = lane >> 3;
    int f = lane & 7;
    int beg = g_indptr[w], end = g_indptr[w + 1];
    float acc = 0.f;
    for (int e0 = beg; e0 < end; e0 += 4) {
        int e = e0 + g;
        if (e < end) {
            int2 m = __ldg(&g_mw[e]);
            acc += __int_as_float(m.y) * g_h0[m.x * 8 + f];
        }
    }
    acc += __shfl_xor_sync(0xFFFFFFFFu, acc, 8);
    acc += __shfl_xor_sync(0xFFFFFFFFu, acc, 16);
    if (lane < 8) {
        float dv = g_dinvw[w];
        g_agg8[w * 8 + f] = dv * (acc + dv * g_h0[w * 8 + f]);
    }
}

// Aggregate 64-feature tensor. Warp per node; each 16-lane half owns one edge
// of a pair, 4 edges in flight per iteration for MLP depth.
__global__ void k_agg64(const float* __restrict__ h, float* __restrict__ agg, int n) {
    int w = (blockIdx.x * blockDim.x + threadIdx.x) >> 5;
    if (w >= n) return;
    int lane = threadIdx.x & 31;
    int half = lane >> 4;
    int l16 = lane & 15;
    int beg = g_indptr[w], end = g_indptr[w + 1];
    float4 acc = make_float4(0.f, 0.f, 0.f, 0.f);
    int e = beg;
    for (; e + 4 <= end; e += 4) {
        int2 m0 = __ldg(&g_mw[e + half]);
        int2 m1 = __ldg(&g_mw[e + 2 + half]);
        float4 v0 = __ldg((const float4*)(h + (size_t)m0.x * 64) + l16);
        float4 v1 = __ldg((const float4*)(h + (size_t)m1.x * 64) + l16);
        float c0 = __int_as_float(m0.y);
        float c1 = __int_as_float(m1.y);
        acc.x = fmaf(c0, v0.x, acc.x); acc.y = fmaf(c0, v0.y, acc.y);
        acc.z = fmaf(c0, v0.z, acc.z); acc.w = fmaf(c0, v0.w, acc.w);
        acc.x = fmaf(c1, v1.x, acc.x); acc.y = fmaf(c1, v1.y, acc.y);
        acc.z = fmaf(c1, v1.z, acc.z); acc.w = fmaf(c1, v1.w, acc.w);
    }
    for (; e + 2 <= end; e += 2) {
        int2 m = __ldg(&g_mw[e + half]);
        float4 v = __ldg((const float4*)(h + (size_t)m.x * 64) + l16);
        float c0 = __int_as_float(m.y);
        acc.x = fmaf(c0, v.x, acc.x); acc.y = fmaf(c0, v.y, acc.y);
        acc.z = fmaf(c0, v.z, acc.z); acc.w = fmaf(c0, v.w, acc.w);
    }
    if (e < end && half == 0) {
        int2 m = __ldg(&g_mw[e]);
        float4 v = __ldg((const float4*)(h + (size_t)m.x * 64) + l16);
        float c0 = __int_as_float(m.y);
        acc.x = fmaf(c0, v.x, acc.x); acc.y = fmaf(c0, v.y, acc.y);
        acc.z = fmaf(c0, v.z, acc.z); acc.w = fmaf(c0, v.w, acc.w);
    }
    acc.x += __shfl_down_sync(0xFFFFFFFFu, acc.x, 16);
    acc.y += __shfl_down_sync(0xFFFFFFFFu, acc.y, 16);
    acc.z += __shfl_down_sync(0xFFFFFFFFu, acc.z, 16);
    acc.w += __shfl_down_sync(0xFFFFFFFFu, acc.w, 16);
    if (half == 0) {
        float dv = g_dinvw[w];
        float4 sv = __ldg((const float4*)(h + (size_t)w * 64) + l16);
        float4 o;
        o.x = dv * (acc.x + dv * sv.x);
        o.y = dv * (acc.y + dv * sv.y);
        o.z = dv * (acc.z + dv * sv.z);
        o.w = dv * (acc.w + dv * sv.w);
        ((float4*)(agg + (size_t)w * 64))[l16] = o;
    }
}

// GEMM [n,F] x [F,64] + bias + softplus. W columns live in registers.
template <int F>
__global__ void k_gemm(const float* __restrict__ in, const float* __restrict__ W,
                       const float* __restrict__ b, float* __restrict__ out, int n) {
    __shared__ float sIn[4 * F];
    int o = threadIdx.x & 63;
    int nl = threadIdx.x >> 6;   // 0..3
    float wreg[F];
    #pragma unroll
    for (int f = 0; f < F; f++) wreg[f] = W[f * 64 + o];
    float bias = b[o];
    int base = blockIdx.x * 128;
    for (int k = 0; k < 128; k += 4) {
        __syncthreads();
        for (int i = threadIdx.x; i < 4 * F; i += 256) {
            int node = base + k + i / F;
            sIn[i] = (node < n) ? in[(size_t)node * F + (i % F)] : 0.f;
        }
        __syncthreads();
        int node = base + k + nl;
        if (node < n) {
            float acc = bias;
            #pragma unroll
            for (int f = 0; f < F; f++) acc = fmaf(sIn[nl * F + f], wreg[f], acc);
            out[(size_t)node * 64 + o] = softplus_f(acc);
        }
    }
}

// Layer-3 GEMM fused with the output projection:
// s1[node] = dinv1[node] * sum_o softplus(gemm_o) * Wout[o]. h3 never hits memory.
__global__ void k_gemm_wout(const float* __restrict__ in, const float* __restrict__ W,
                            const float* __restrict__ b, const float* __restrict__ Wout,
                            int n) {
    __shared__ float sIn[4 * 64];
    __shared__ float red[8];
    int o = threadIdx.x & 63;
    int nl = threadIdx.x >> 6;   // 0..3
    float wreg[64];
    #pragma unroll
    for (int f = 0; f < 64; f++) wreg[f] = W[f * 64 + o];
    float bias = b[o];
    float wo = Wout[o];
    int base = blockIdx.x * 128;
    for (int k = 0; k < 128; k += 4) {
        __syncthreads();
        for (int i = threadIdx.x; i < 4 * 64; i += 256) {
            int node = base + k + i / 64;
            sIn[i] = (node < n) ? in[(size_t)node * 64 + (i % 64)] : 0.f;
        }
        __syncthreads();
        int node = base + k + nl;
        float part = 0.f;
        if (node < n) {
            float acc = bias;
            #pragma unroll
            for (int f = 0; f < 64; f++) acc = fmaf(sIn[nl * 64 + f], wreg[f], acc);
            part = softplus_f(acc) * wo;
        }
        float ws = warp_sum(part);
        if ((threadIdx.x & 31) == 0) red[threadIdx.x >> 5] = ws;
        __syncthreads();
        if (o == 0 && node < n)
            g_s1[node] = g_dinv1[node] * (red[nl * 2] + red[nl * 2 + 1]);
    }
}

// out[n] = bout + dinv1[n] * (s1[n] + sum_e s1[row[e]])   (warp per node)
__global__ void k_out(const float* __restrict__ bout, float* __restrict__ out, int n) {
    int w = (blockIdx.x * blockDim.x + threadIdx.x) >> 5;
    if (w >= n) return;
    int lane = threadIdx.x & 31;
    int beg = g_indptr[w], end = g_indptr[w + 1];
    float acc = 0.f;
    for (int e = beg + lane; e < end; e += 32) {
        int r = __ldg(&g_mw[e]).x;
        acc += g_s1[r];
    }
    acc = warp_sum(acc);
    if (lane == 0)
        out[w] = bout[0] + g_dinv1[w] * (acc + g_s1[w]);
}

// ---------------- launch ----------------
extern "C" void kernel_launch(void* const* d_in, const int* in_sizes, int n_in,
                              void* d_out, int out_size) {
    (void)n_in; (void)out_size;
    const void*  edge_idx = d_in[8];
    const float* edge_d   = (const float*)d_in[9];
    const float* x    = (const float*)d_in[1];
    const float* dtr  = (const float*)d_in[2];
    const float* npd  = (const float*)d_in[3];
    const float* kp   = (const float*)d_in[4];
    const float* kpp  = (const float*)d_in[5];
    const float* imin = (const float*)d_in[6];
    const float* imax = (const float*)d_in[7];
    const float* W1 = (const float*)d_in[10];
    const float* b1 = (const float*)d_in[11];
    const float* W2 = (const float*)d_in[12];
    const float* b2 = (const float*)d_in[13];
    const float* W3 = (const float*)d_in[14];
    const float* b3 = (const float*)d_in[15];
    const float* Wout = (const float*)d_in[16];
    const float* bout = (const float*)d_in[17];

    int N = in_sizes[1] / 2;          // x is [N,2]
    int E = in_sizes[9];              // edge_distance is [E]
    if (N > NMAX) N = NMAX;
    if (E > EMAX) E = EMAX;

    float *pA = nullptr, *pB = nullptr, *pAgg8 = nullptr;
    cudaGetSymbolAddress((void**)&pA, g_A);
    cudaGetSymbolAddress((void**)&pB, g_B);
    cudaGetSymbolAddress((void**)&pAgg8, g_agg8);

    const int T = 256;
    int gN  = (N + T - 1) / T;
    int gE  = (E + T - 1) / T;
    int gW  = (N * 32 + T - 1) / T;       // warp-per-node kernels
    int gG  = (N + 127) / 128;            // gemm blocks
    int nb  = (N + 1023) / 1024;          // scan blocks

    k_init_detect<<<gN, T>>>((const int*)edge_idx, N);
    k_convert<<<gE, T>>>(edge_idx, edge_d, E);
    k_bsum<<<nb, 256>>>(N);
    k_bscan<<<1, 128>>>(nb, N);
    k_fill<<<nb, 256>>>(x, dtr, npd, kp, kpp, imin, imax, N);
    k_place<<<gE, T>>>(edge_idx, edge_d, E);

    // Layer 1: aggregate 8 feats, then GEMM(8->64)+softplus
    k_agg8<<<gW, T>>>(N);
    k_gemm<8><<<gG, 256>>>(pAgg8, W1, b1, pA, N);

    // Layer 2
    k_agg64<<<gW, T>>>(pA, pB, N);
    k_gemm<64><<<gG, 256>>>(pB, W2, b2, pA, N);

    // Layer 3 (output projection fused into the GEMM)
    k_agg64<<<gW, T>>>(pA, pB, N);
    k_gemm_wout<<<gG, 256>>>(pB, W3, b3, Wout, N);

    // Output conv aggregation with ones-norms
    k_out<<<gW, T>>>(bout, (float*)d_out, N);
}

// round 4
// speedup vs baseline: 1.6502x; 1.0827x over previous
#include <cuda_runtime.h>
#include <math.h>
#include <stdint.h>

// GCN: 4 layers over N=100000 nodes, E=3200000 edges.
// CSR-by-col build per launch, warp-per-node aggregation with vectorized
// gathers, aggregate-then-GEMM on the cheap side. Layer-1 GEMM fused into the
// 8-feature aggregation; output projection fused into the layer-3 GEMM.

#define NMAX 100000
#define EMAX 3200000

// ---------------- scratch (static __device__, no allocations) ----------------
__device__ int   g_is64;
__device__ float g_degw[NMAX];
__device__ int   g_cnt[NMAX + 4];
__device__ float g_dinvw[NMAX];
__device__ float g_dinv1[NMAX];
__device__ int   g_indptr[NMAX + 1];
__device__ int   g_cursor[NMAX];
__device__ int   g_bsum[128];
__device__ int2  g_mw[EMAX];        // {row, __float_as_int(dinvw[row]*w)}
__device__ float g_h0[NMAX * 8];
__device__ float g_A[NMAX * 64];
__device__ float g_B[NMAX * 64];
__device__ float g_s1[NMAX];        // dinv1[n] * (h3[n] . Wout)

// ---------------- helpers ----------------
__device__ __forceinline__ float softplus_f(float x) {
    return fmaxf(x, 0.f) + log1pf(expf(-fabsf(x)));
}

__device__ __forceinline__ float warp_sum(float v) {
    #pragma unroll
    for (int off = 16; off > 0; off >>= 1)
        v += __shfl_down_sync(0xFFFFFFFFu, v, off);
    return v;
}

// ---------------- kernels ----------------

// Init degree arrays; block 0 additionally detects int64 vs int32 edge_index.
__global__ void k_init_detect(const int* __restrict__ p, int n) {
    int i = blockIdx.x * blockDim.x + threadIdx.x;
    if (i < n) {
        g_degw[i] = 1.0f;   // self-loop weight
        g_cnt[i] = 0;
    }
    if (blockIdx.x == 0) {
        __shared__ int zc;
        if (threadIdx.x == 0) zc = 0;
        __syncthreads();
        int local = 0;
        for (int j = threadIdx.x; j < 1024; j += blockDim.x)
            if (p[2 * j + 1] == 0) local++;
        atomicAdd(&zc, local);
        __syncthreads();
        if (threadIdx.x == 0) g_is64 = (zc > 1000) ? 1 : 0;
    }
}

// Pass 1: histogram weighted/unweighted in-degree (only needs col + weight).
__global__ void k_convert(const void* __restrict__ idx,
                          const float* __restrict__ dist, int E) {
    int e = blockIdx.x * blockDim.x + threadIdx.x;
    if (e >= E) return;
    int c;
    if (g_is64) c = (int)((const long long*)idx)[e + E];
    else        c = ((const int*)idx)[e + E];
    float w = 1.0f / (dist[e] + 1e-6f);
    atomicAdd(&g_degw[c], w);
    atomicAdd(&g_cnt[c], 1);
}

// Scan stage A: per-block sums of g_cnt (1024 counts per block, coalesced).
__global__ void k_bsum(int n) {
    int t = threadIdx.x;
    int i0 = blockIdx.x * 1024 + t * 4;
    int s = 0;
    if (i0 + 3 < n) {
        int4 v = *(const int4*)&g_cnt[i0];
        s = v.x + v.y + v.z + v.w;
    } else {
        #pragma unroll
        for (int j = 0; j < 4; j++) { int i = i0 + j; if (i < n) s += g_cnt[i]; }
    }
    #pragma unroll
    for (int off = 16; off > 0; off >>= 1)
        s += __shfl_down_sync(0xFFFFFFFFu, s, off);
    __shared__ int ws[8];
    if ((t & 31) == 0) ws[t >> 5] = s;
    __syncthreads();
    if (t == 0) {
        int tot = 0;
        #pragma unroll
        for (int k = 0; k < 8; k++) tot += ws[k];
        g_bsum[blockIdx.x] = tot;
    }
}

// Scan stage B (inlined per block) + fused per-node work:
// indptr/cursor, dinvw/dinv1, H0 build.
__global__ void k_fill(const float* __restrict__ x,
                       const float* __restrict__ dtr,
                       const float* __restrict__ npd,
                       const float* __restrict__ kp,
                       const float* __restrict__ kpp,
                       const float* __restrict__ imin,
                       const float* __restrict__ imax, int n, int nb) {
    __shared__ int sh[128];
    int t = threadIdx.x;
    if (t < 128) sh[t] = (t < nb) ? g_bsum[t] : 0;
    __syncthreads();
    #pragma unroll
    for (int off = 1; off < 128; off <<= 1) {
        int u = (t < 128 && t >= off) ? sh[t - off] : 0;
        __syncthreads();
        if (t < 128) sh[t] += u;
        __syncthreads();
    }
    __shared__ int blockExcl, totalE;
    if (t == 0) {
        blockExcl = (blockIdx.x == 0) ? 0 : sh[blockIdx.x - 1];
        totalE = sh[nb - 1];
    }
    __syncthreads();

    int lane = t & 31;
    int warp = t >> 5;
    int i0 = blockIdx.x * 1024 + t * 4;

    int c[4];
    #pragma unroll
    for (int j = 0; j < 4; j++) {
        int i = i0 + j;
        c[j] = (i < n) ? g_cnt[i] : 0;
    }
    int tsum = c[0] + c[1] + c[2] + c[3];

    // warp-inclusive scan of per-thread sums
    int inc = tsum;
    #pragma unroll
    for (int off = 1; off < 32; off <<= 1) {
        int u = __shfl_up_sync(0xFFFFFFFFu, inc, off);
        if (lane >= off) inc += u;
    }
    __shared__ int wsum[8];
    if (lane == 31) wsum[warp] = inc;
    __syncthreads();
    int woff = 0;
    for (int k = 0; k < warp; k++) woff += wsum[k];

    int excl = blockExcl + woff + (inc - tsum);
    #pragma unroll
    for (int j = 0; j < 4; j++) {
        int i = i0 + j;
        if (i < n) {
            g_indptr[i] = excl;
            g_cursor[i] = excl;
            g_dinvw[i] = rsqrtf(g_degw[i]);
            g_dinv1[i] = rsqrtf((float)c[j] + 1.f);
            float2 xv = ((const float2*)x)[i];
            float4 a = make_float4(xv.x, xv.y, dtr[i], npd[i]);
            float4 b = make_float4(kp[i], kpp[i], imin[i], imax[i]);
            ((float4*)g_h0)[2 * i] = a;
            ((float4*)g_h0)[2 * i + 1] = b;
            if (i == n - 1) g_indptr[n] = totalE;
            excl += c[j];
        }
    }
}

// Pass 2: place edges into CSR order with precomputed source-side coefficient.
// Full norm for (r->c) is dinvw[r]*w*dinvw[c]; dinvw[c] is applied per node
// in the aggregation kernels.
__global__ void k_place(const void* __restrict__ idx,
                        const float* __restrict__ dist, int E) {
    int e = blockIdx.x * blockDim.x + threadIdx.x;
    if (e >= E) return;
    int r, c;
    if (g_is64) {
        const long long* p = (const long long*)idx;
        r = (int)p[e];
        c = (int)p[e + E];
    } else {
        const int* p = (const int*)idx;
        r = p[e];
        c = p[e + E];
    }
    float w = 1.0f / (dist[e] + 1e-6f);
    int pos = atomicAdd(&g_cursor[c], 1);
    g_mw[pos] = make_int2(r, __float_as_int(g_dinvw[r] * w));
}

// Layer 1 fused: aggregate 8-feature H0 (warp per node, 4 edges/iter), then
// in-warp GEMM(8->64)+bias+softplus with W1 staged in shared memory.
__global__ __launch_bounds__(256) void k_agg8_gemm1(
        const float* __restrict__ W1, const float* __restrict__ b1,
        float* __restrict__ outA, int n) {
    __shared__ float w1s[8 * 64];
    __shared__ float b1s[64];
    int t = threadIdx.x;
    for (int i = t; i < 512; i += 256) w1s[i] = W1[i];
    if (t < 64) b1s[t] = b1[t];
    __syncthreads();

    int w = (blockIdx.x * 256 + t) >> 5;
    if (w >= n) return;
    int lane = t & 31;
    int g = lane >> 3;
    int f = lane & 7;
    int beg = g_indptr[w], end = g_indptr[w + 1];
    float acc = 0.f;
    for (int e0 = beg; e0 < end; e0 += 4) {
        int e = e0 + g;
        if (e < end) {
            int2 m = __ldg(&g_mw[e]);
            acc += __int_as_float(m.y) * g_h0[m.x * 8 + f];
        }
    }
    acc += __shfl_xor_sync(0xFFFFFFFFu, acc, 8);
    acc += __shfl_xor_sync(0xFFFFFFFFu, acc, 16);
    float dv = g_dinvw[w];
    float val = dv * (acc + dv * g_h0[w * 8 + f]);   // lane holds f = lane&7

    float a[8];
    #pragma unroll
    for (int k = 0; k < 8; k++) a[k] = __shfl_sync(0xFFFFFFFFu, val, k);

    float s0 = b1s[lane], s1 = b1s[lane + 32];
    #pragma unroll
    for (int k = 0; k < 8; k++) {
        s0 = fmaf(a[k], w1s[k * 64 + lane], s0);
        s1 = fmaf(a[k], w1s[k * 64 + lane + 32], s1);
    }
    outA[(size_t)w * 64 + lane]      = softplus_f(s0);
    outA[(size_t)w * 64 + lane + 32] = softplus_f(s1);
}

// Aggregate 64-feature tensor. Warp per node; each 16-lane half owns one edge
// of a pair, 4 edges in flight per iteration for MLP depth.
__global__ __launch_bounds__(256) void k_agg64(
        const float* __restrict__ h, float* __restrict__ agg, int n) {
    int w = (blockIdx.x * blockDim.x + threadIdx.x) >> 5;
    if (w >= n) return;
    int lane = threadIdx.x & 31;
    int half = lane >> 4;
    int l16 = lane & 15;
    int beg = g_indptr[w], end = g_indptr[w + 1];
    float4 acc = make_float4(0.f, 0.f, 0.f, 0.f);
    int e = beg;
    for (; e + 4 <= end; e += 4) {
        int2 m0 = __ldg(&g_mw[e + half]);
        int2 m1 = __ldg(&g_mw[e + 2 + half]);
        float4 v0 = __ldg((const float4*)(h + (size_t)m0.x * 64) + l16);
        float4 v1 = __ldg((const float4*)(h + (size_t)m1.x * 64) + l16);
        float c0 = __int_as_float(m0.y);
        float c1 = __int_as_float(m1.y);
        acc.x = fmaf(c0, v0.x, acc.x); acc.y = fmaf(c0, v0.y, acc.y);
        acc.z = fmaf(c0, v0.z, acc.z); acc.w = fmaf(c0, v0.w, acc.w);
        acc.x = fmaf(c1, v1.x, acc.x); acc.y = fmaf(c1, v1.y, acc.y);
        acc.z = fmaf(c1, v1.z, acc.z); acc.w = fmaf(c1, v1.w, acc.w);
    }
    for (; e + 2 <= end; e += 2) {
        int2 m = __ldg(&g_mw[e + half]);
        float4 v = __ldg((const float4*)(h + (size_t)m.x * 64) + l16);
        float c0 = __int_as_float(m.y);
        acc.x = fmaf(c0, v.x, acc.x); acc.y = fmaf(c0, v.y, acc.y);
        acc.z = fmaf(c0, v.z, acc.z); acc.w = fmaf(c0, v.w, acc.w);
    }
    if (e < end && half == 0) {
        int2 m = __ldg(&g_mw[e]);
        float4 v = __ldg((const float4*)(h + (size_t)m.x * 64) + l16);
        float c0 = __int_as_float(m.y);
        acc.x = fmaf(c0, v.x, acc.x); acc.y = fmaf(c0, v.y, acc.y);
        acc.z = fmaf(c0, v.z, acc.z); acc.w = fmaf(c0, v.w, acc.w);
    }
    acc.x += __shfl_down_sync(0xFFFFFFFFu, acc.x, 16);
    acc.y += __shfl_down_sync(0xFFFFFFFFu, acc.y, 16);
    acc.z += __shfl_down_sync(0xFFFFFFFFu, acc.z, 16);
    acc.w += __shfl_down_sync(0xFFFFFFFFu, acc.w, 16);
    if (half == 0) {
        float dv = g_dinvw[w];
        float4 sv = __ldg((const float4*)(h + (size_t)w * 64) + l16);
        float4 o;
        o.x = dv * (acc.x + dv * sv.x);
        o.y = dv * (acc.y + dv * sv.y);
        o.z = dv * (acc.z + dv * sv.z);
        o.w = dv * (acc.w + dv * sv.w);
        ((float4*)(agg + (size_t)w * 64))[l16] = o;
    }
}

// GEMM [n,64] x [64,64] + bias + softplus. W columns in registers,
// 8-row smem stages with float4 fills.
__global__ __launch_bounds__(256) void k_gemm64(
        const float* __restrict__ in, const float* __restrict__ W,
        const float* __restrict__ b, float* __restrict__ out, int n) {
    __shared__ float sIn[8 * 64];
    int o = threadIdx.x & 63;
    int nl = threadIdx.x >> 6;   // 0..3
    float wreg[64];
    #pragma unroll
    for (int f = 0; f < 64; f++) wreg[f] = W[f * 64 + o];
    float bias = b[o];
    int base = blockIdx.x * 128;
    for (int k = 0; k < 128; k += 8) {
        __syncthreads();
        if (threadIdx.x < 128) {
            int rr = threadIdx.x >> 4;
            int cc = threadIdx.x & 15;
            int node = base + k + rr;
            float4 v = (node < n) ? __ldg((const float4*)(in + (size_t)node * 64) + cc)
                                  : make_float4(0.f, 0.f, 0.f, 0.f);
            ((float4*)sIn)[threadIdx.x] = v;
        }
        __syncthreads();
        #pragma unroll
        for (int s = 0; s < 2; s++) {
            int r = nl + s * 4;
            int node = base + k + r;
            if (node < n) {
                float acc = bias;
                #pragma unroll
                for (int f = 0; f < 64; f++) acc = fmaf(sIn[r * 64 + f], wreg[f], acc);
                out[(size_t)node * 64 + o] = softplus_f(acc);
            }
        }
    }
}

// Layer-3 GEMM fused with the output projection:
// s1[node] = dinv1[node] * sum_o softplus(gemm_o) * Wout[o]. h3 never hits memory.
__global__ __launch_bounds__(256) void k_gemm_wout(
        const float* __restrict__ in, const float* __restrict__ W,
        const float* __restrict__ b, const float* __restrict__ Wout, int n) {
    __shared__ float sIn[8 * 64];
    __shared__ float red[8];
    int o = threadIdx.x & 63;
    int nl = threadIdx.x >> 6;   // 0..3
    float wreg[64];
    #pragma unroll
    for (int f = 0; f < 64; f++) wreg[f] = W[f * 64 + o];
    float bias = b[o];
    float wo = Wout[o];
    int base = blockIdx.x * 128;
    for (int k = 0; k < 128; k += 8) {
        __syncthreads();
        if (threadIdx.x < 128) {
            int rr = threadIdx.x >> 4;
            int cc = threadIdx.x & 15;
            int node = base + k + rr;
            float4 v = (node < n) ? __ldg((const float4*)(in + (size_t)node * 64) + cc)
                                  : make_float4(0.f, 0.f, 0.f, 0.f);
            ((float4*)sIn)[threadIdx.x] = v;
        }
        __syncthreads();
        #pragma unroll
        for (int s = 0; s < 2; s++) {
            int r = nl + s * 4;
            int node = base + k + r;
            float part = 0.f;
            if (node < n) {
                float acc = bias;
                #pragma unroll
                for (int f = 0; f < 64; f++) acc = fmaf(sIn[r * 64 + f], wreg[f], acc);
                part = softplus_f(acc) * wo;
            }
            float ws = warp_sum(part);
            if ((threadIdx.x & 31) == 0) red[threadIdx.x >> 5] = ws;
            __syncthreads();
            if (o == 0 && node < n)
                g_s1[node] = g_dinv1[node] * (red[nl * 2] + red[nl * 2 + 1]);
            __syncthreads();
        }
    }
}

// out[n] = bout + dinv1[n] * (s1[n] + sum_e s1[row[e]])   (warp per node)
__global__ __launch_bounds__(256) void k_out(
        const float* __restrict__ bout, float* __restrict__ out, int n) {
    int w = (blockIdx.x * blockDim.x + threadIdx.x) >> 5;
    if (w >= n) return;
    int lane = threadIdx.x & 31;
    int beg = g_indptr[w], end = g_indptr[w + 1];
    float acc = 0.f;
    for (int e = beg + lane; e < end; e += 32) {
        int r = __ldg(&g_mw[e]).x;
        acc += g_s1[r];
    }
    acc = warp_sum(acc);
    if (lane == 0)
        out[w] = bout[0] + g_dinv1[w] * (acc + g_s1[w]);
}

// ---------------- launch ----------------
extern "C" void kernel_launch(void* const* d_in, const int* in_sizes, int n_in,
                              void* d_out, int out_size) {
    (void)n_in; (void)out_size;
    const void*  edge_idx = d_in[8];
    const float* edge_d   = (const float*)d_in[9];
    const float* x    = (const float*)d_in[1];
    const float* dtr  = (const float*)d_in[2];
    const float* npd  = (const float*)d_in[3];
    const float* kp   = (const float*)d_in[4];
    const float* kpp  = (const float*)d_in[5];
    const float* imin = (const float*)d_in[6];
    const float* imax = (const float*)d_in[7];
    const float* W1 = (const float*)d_in[10];
    const float* b1 = (const float*)d_in[11];
    const float* W2 = (const float*)d_in[12];
    const float* b2 = (const float*)d_in[13];
    const float* W3 = (const float*)d_in[14];
    const float* b3 = (const float*)d_in[15];
    const float* Wout = (const float*)d_in[16];
    const float* bout = (const float*)d_in[17];

    int N = in_sizes[1] / 2;          // x is [N,2]
    int E = in_sizes[9];              // edge_distance is [E]
    if (N > NMAX) N = NMAX;
    if (E > EMAX) E = EMAX;

    float *pA = nullptr, *pB = nullptr;
    cudaGetSymbolAddress((void**)&pA, g_A);
    cudaGetSymbolAddress((void**)&pB, g_B);

    const int T = 256;
    int gN  = (N + T - 1) / T;
    int gE  = (E + T - 1) / T;
    int gW  = (N * 32 + T - 1) / T;       // warp-per-node kernels
    int gG  = (N + 127) / 128;            // gemm blocks
    int nb  = (N + 1023) / 1024;          // scan blocks

    k_init_detect<<<gN, T>>>((const int*)edge_idx, N);
    k_convert<<<gE, T>>>(edge_idx, edge_d, E);
    k_bsum<<<nb, 256>>>(N);
    k_fill<<<nb, 256>>>(x, dtr, npd, kp, kpp, imin, imax, N, nb);
    k_place<<<gE, T>>>(edge_idx, edge_d, E);

    // Layer 1: fused aggregate(8) + GEMM(8->64) + softplus
    k_agg8_gemm1<<<gW, T>>>(W1, b1, pA, N);

    // Layer 2
    k_agg64<<<gW, T>>>(pA, pB, N);
    k_gemm64<<<gG, 256>>>(pB, W2, b2, pA, N);

    // Layer 3 (output projection fused into the GEMM)
    k_agg64<<<gW, T>>>(pA, pB, N);
    k_gemm_wout<<<gG, 256>>>(pB, W3, b3, Wout, N);

    // Output conv aggregation with ones-norms
    k_out<<<gW, T>>>(bout, (float*)d_out, N);
}

// round 6
// speedup vs baseline: 1.7180x; 1.0411x over previous
#include <cuda_runtime.h>
#include <cuda_fp16.h>
#include <math.h>
#include <stdint.h>

// GCN: 4 layers over N=100000 nodes, E=3200000 edges.
// CSR-by-col build per launch; warp-per-node aggregation gathering from fp16
// activation tables (ONLY quantization points; fp32 accumulate everywhere,
// aggregates/GEMM stay fp32). Layer-1 GEMM fused into the 8-feature
// aggregation; output projection fused into the layer-3 GEMM.

#define NMAX 100000
#define EMAX 3200000

// ---------------- scratch (static __device__, no allocations) ----------------
__device__ int   g_is64;
__device__ float g_degw[NMAX];
__device__ int   g_cnt[NMAX + 4];
__device__ float g_dinvw[NMAX];
__device__ float g_dinv1[NMAX];
__device__ int   g_indptr[NMAX + 1];
__device__ int   g_cursor[NMAX];
__device__ int   g_bsum[128];
__device__ int2  g_mw[EMAX];            // {row, __float_as_int(dinvw[row]*w)}
__device__ float g_h0[NMAX * 8];
__device__ __half g_H[NMAX * 64];       // fp16 activation table (h1, then h2)
__device__ float g_Agg[NMAX * 64];      // fp32 aggregate buffer
__device__ float g_s1[NMAX];            // dinv1[n] * (h3[n] . Wout)

// ---------------- helpers ----------------
__device__ __forceinline__ float softplus_f(float x) {
    return fmaxf(x, 0.f) + log1pf(expf(-fabsf(x)));
}

__device__ __forceinline__ float warp_sum(float v) {
    #pragma unroll
    for (int off = 16; off > 0; off >>= 1)
        v += __shfl_down_sync(0xFFFFFFFFu, v, off);
    return v;
}

// ---------------- kernels ----------------

// Init degree arrays; block 0 additionally detects int64 vs int32 edge_index.
__global__ void k_init_detect(const int* __restrict__ p, int n) {
    int i = blockIdx.x * blockDim.x + threadIdx.x;
    if (i < n) {
        g_degw[i] = 1.0f;   // self-loop weight
        g_cnt[i] = 0;
    }
    if (blockIdx.x == 0) {
        __shared__ int zc;
        if (threadIdx.x == 0) zc = 0;
        __syncthreads();
        int local = 0;
        for (int j = threadIdx.x; j < 1024; j += blockDim.x)
            if (p[2 * j + 1] == 0) local++;
        atomicAdd(&zc, local);
        __syncthreads();
        if (threadIdx.x == 0) g_is64 = (zc > 1000) ? 1 : 0;
    }
}

// Pass 1: histogram weighted/unweighted in-degree (only needs col + weight).
__global__ void k_convert(const void* __restrict__ idx,
                          const float* __restrict__ dist, int E) {
    int e = blockIdx.x * blockDim.x + threadIdx.x;
    if (e >= E) return;
    int c;
    if (g_is64) c = (int)((const long long*)idx)[e + E];
    else        c = ((const int*)idx)[e + E];
    float w = 1.0f / (dist[e] + 1e-6f);
    atomicAdd(&g_degw[c], w);
    atomicAdd(&g_cnt[c], 1);
}

// Scan stage A: per-block sums of g_cnt (1024 counts per block, coalesced).
__global__ void k_bsum(int n) {
    int t = threadIdx.x;
    int i0 = blockIdx.x * 1024 + t * 4;
    int s = 0;
    if (i0 + 3 < n) {
        int4 v = *(const int4*)&g_cnt[i0];
        s = v.x + v.y + v.z + v.w;
    } else {
        #pragma unroll
        for (int j = 0; j < 4; j++) { int i = i0 + j; if (i < n) s += g_cnt[i]; }
    }
    #pragma unroll
    for (int off = 16; off > 0; off >>= 1)
        s += __shfl_down_sync(0xFFFFFFFFu, s, off);
    __shared__ int ws[8];
    if ((t & 31) == 0) ws[t >> 5] = s;
    __syncthreads();
    if (t == 0) {
        int tot = 0;
        #pragma unroll
        for (int k = 0; k < 8; k++) tot += ws[k];
        g_bsum[blockIdx.x] = tot;
    }
}

// Scan stage B (inlined per block) + fused per-node work:
// indptr/cursor, dinvw/dinv1, H0 build.
__global__ void k_fill(const float* __restrict__ x,
                       const float* __restrict__ dtr,
                       const float* __restrict__ npd,
                       const float* __restrict__ kp,
                       const float* __restrict__ kpp,
                       const float* __restrict__ imin,
                       const float* __restrict__ imax, int n, int nb) {
    __shared__ int sh[128];
    int t = threadIdx.x;
    if (t < 128) sh[t] = (t < nb) ? g_bsum[t] : 0;
    __syncthreads();
    #pragma unroll
    for (int off = 1; off < 128; off <<= 1) {
        int u = (t < 128 && t >= off) ? sh[t - off] : 0;
        __syncthreads();
        if (t < 128) sh[t] += u;
        __syncthreads();
    }
    __shared__ int blockExcl, totalE;
    if (t == 0) {
        blockExcl = (blockIdx.x == 0) ? 0 : sh[blockIdx.x - 1];
        totalE = sh[nb - 1];
    }
    __syncthreads();

    int lane = t & 31;
    int warp = t >> 5;
    int i0 = blockIdx.x * 1024 + t * 4;

    int c[4];
    #pragma unroll
    for (int j = 0; j < 4; j++) {
        int i = i0 + j;
        c[j] = (i < n) ? g_cnt[i] : 0;
    }
    int tsum = c[0] + c[1] + c[2] + c[3];

    int inc = tsum;
    #pragma unroll
    for (int off = 1; off < 32; off <<= 1) {
        int u = __shfl_up_sync(0xFFFFFFFFu, inc, off);
        if (lane >= off) inc += u;
    }
    __shared__ int wsum[8];
    if (lane == 31) wsum[warp] = inc;
    __syncthreads();
    int woff = 0;
    for (int k = 0; k < warp; k++) woff += wsum[k];

    int excl = blockExcl + woff + (inc - tsum);
    #pragma unroll
    for (int j = 0; j < 4; j++) {
        int i = i0 + j;
        if (i < n) {
            g_indptr[i] = excl;
            g_cursor[i] = excl;
            g_dinvw[i] = rsqrtf(g_degw[i]);
            g_dinv1[i] = rsqrtf((float)c[j] + 1.f);
            float2 xv = ((const float2*)x)[i];
            float4 a = make_float4(xv.x, xv.y, dtr[i], npd[i]);
            float4 b = make_float4(kp[i], kpp[i], imin[i], imax[i]);
            ((float4*)g_h0)[2 * i] = a;
            ((float4*)g_h0)[2 * i + 1] = b;
            if (i == n - 1) g_indptr[n] = totalE;
            excl += c[j];
        }
    }
}

// Pass 2: place edges into CSR order with precomputed source-side coefficient.
__global__ void k_place(const void* __restrict__ idx,
                        const float* __restrict__ dist, int E) {
    int e = blockIdx.x * blockDim.x + threadIdx.x;
    if (e >= E) return;
    int r, c;
    if (g_is64) {
        const long long* p = (const long long*)idx;
        r = (int)p[e];
        c = (int)p[e + E];
    } else {
        const int* p = (const int*)idx;
        r = p[e];
        c = p[e + E];
    }
    float w = 1.0f / (dist[e] + 1e-6f);
    int pos = atomicAdd(&g_cursor[c], 1);
    g_mw[pos] = make_int2(r, __float_as_int(g_dinvw[r] * w));
}

// Layer 1 fused: aggregate 8-feature H0 (warp per node, 4 edges/iter), then
// in-warp GEMM(8->64)+bias+softplus; output written to the fp16 table.
__global__ __launch_bounds__(256) void k_agg8_gemm1(
        const float* __restrict__ W1, const float* __restrict__ b1,
        __half* __restrict__ outH, int n) {
    __shared__ float w1s[8 * 64];
    __shared__ float b1s[64];
    int t = threadIdx.x;
    for (int i = t; i < 512; i += 256) w1s[i] = W1[i];
    if (t < 64) b1s[t] = b1[t];
    __syncthreads();

    int w = (blockIdx.x * 256 + t) >> 5;
    if (w >= n) return;
    int lane = t & 31;
    int g = lane >> 3;
    int f = lane & 7;
    int beg = g_indptr[w], end = g_indptr[w + 1];
    float acc = 0.f;
    for (int e0 = beg; e0 < end; e0 += 4) {
        int e = e0 + g;
        if (e < end) {
            int2 m = __ldg(&g_mw[e]);
            acc += __int_as_float(m.y) * g_h0[m.x * 8 + f];
        }
    }
    acc += __shfl_xor_sync(0xFFFFFFFFu, acc, 8);
    acc += __shfl_xor_sync(0xFFFFFFFFu, acc, 16);
    float dv = g_dinvw[w];
    float val = dv * (acc + dv * g_h0[w * 8 + f]);   // lane holds f = lane&7

    float a[8];
    #pragma unroll
    for (int k = 0; k < 8; k++) a[k] = __shfl_sync(0xFFFFFFFFu, val, k);

    float s0 = b1s[lane], s1 = b1s[lane + 32];
    #pragma unroll
    for (int k = 0; k < 8; k++) {
        s0 = fmaf(a[k], w1s[k * 64 + lane], s0);
        s1 = fmaf(a[k], w1s[k * 64 + lane + 32], s1);
    }
    outH[(size_t)w * 64 + lane]      = __float2half_rn(softplus_f(s0));
    outH[(size_t)w * 64 + lane + 32] = __float2half_rn(softplus_f(s1));
}

// Aggregate 64-feature fp16 table -> fp32 aggregate. Warp per node; each
// 16-lane half owns one edge of a pair, 4 edges in flight per iteration.
// Lane l16 covers features [4*l16, 4*l16+4). fp32 accumulate.
__global__ __launch_bounds__(256) void k_agg64(
        const __half* __restrict__ h, float* __restrict__ agg, int n) {
    int w = (blockIdx.x * blockDim.x + threadIdx.x) >> 5;
    if (w >= n) return;
    int lane = threadIdx.x & 31;
    int half_id = lane >> 4;
    int l16 = lane & 15;
    int beg = g_indptr[w], end = g_indptr[w + 1];
    float4 acc = make_float4(0.f, 0.f, 0.f, 0.f);
    int e = beg;
    for (; e + 4 <= end; e += 4) {
        int2 m0 = __ldg(&g_mw[e + half_id]);
        int2 m1 = __ldg(&g_mw[e + 2 + half_id]);
        uint2 u0 = __ldg((const uint2*)(h + (size_t)m0.x * 64) + l16);
        uint2 u1 = __ldg((const uint2*)(h + (size_t)m1.x * 64) + l16);
        float c0 = __int_as_float(m0.y);
        float c1 = __int_as_float(m1.y);
        float2 f0a = __half22float2(*(const __half2*)&u0.x);
        float2 f0b = __half22float2(*(const __half2*)&u0.y);
        float2 f1a = __half22float2(*(const __half2*)&u1.x);
        float2 f1b = __half22float2(*(const __half2*)&u1.y);
        acc.x = fmaf(c0, f0a.x, acc.x); acc.y = fmaf(c0, f0a.y, acc.y);
        acc.z = fmaf(c0, f0b.x, acc.z); acc.w = fmaf(c0, f0b.y, acc.w);
        acc.x = fmaf(c1, f1a.x, acc.x); acc.y = fmaf(c1, f1a.y, acc.y);
        acc.z = fmaf(c1, f1b.x, acc.z); acc.w = fmaf(c1, f1b.y, acc.w);
    }
    for (; e + 2 <= end; e += 2) {
        int2 m = __ldg(&g_mw[e + half_id]);
        uint2 u = __ldg((const uint2*)(h + (size_t)m.x * 64) + l16);
        float c0 = __int_as_float(m.y);
        float2 fa = __half22float2(*(const __half2*)&u.x);
        float2 fb = __half22float2(*(const __half2*)&u.y);
        acc.x = fmaf(c0, fa.x, acc.x); acc.y = fmaf(c0, fa.y, acc.y);
        acc.z = fmaf(c0, fb.x, acc.z); acc.w = fmaf(c0, fb.y, acc.w);
    }
    if (e < end && half_id == 0) {
        int2 m = __ldg(&g_mw[e]);
        uint2 u = __ldg((const uint2*)(h + (size_t)m.x * 64) + l16);
        float c0 = __int_as_float(m.y);
        float2 fa = __half22float2(*(const __half2*)&u.x);
        float2 fb = __half22float2(*(const __half2*)&u.y);
        acc.x = fmaf(c0, fa.x, acc.x); acc.y = fmaf(c0, fa.y, acc.y);
        acc.z = fmaf(c0, fb.x, acc.z); acc.w = fmaf(c0, fb.y, acc.w);
    }
    acc.x += __shfl_down_sync(0xFFFFFFFFu, acc.x, 16);
    acc.y += __shfl_down_sync(0xFFFFFFFFu, acc.y, 16);
    acc.z += __shfl_down_sync(0xFFFFFFFFu, acc.z, 16);
    acc.w += __shfl_down_sync(0xFFFFFFFFu, acc.w, 16);
    if (half_id == 0) {
        float dv = g_dinvw[w];
        uint2 su = __ldg((const uint2*)(h + (size_t)w * 64) + l16);
        float2 sa = __half22float2(*(const __half2*)&su.x);
        float2 sb = __half22float2(*(const __half2*)&su.y);
        float4 o;
        o.x = dv * (acc.x + dv * sa.x);
        o.y = dv * (acc.y + dv * sa.y);
        o.z = dv * (acc.z + dv * sb.x);
        o.w = dv * (acc.w + dv * sb.y);
        ((float4*)(agg + (size_t)w * 64))[l16] = o;
    }
}

// GEMM [n,64](fp32) x [64,64] + bias + softplus -> fp16 table. W in registers,
// 8-row smem stages with float4 fills.
__global__ __launch_bounds__(256) void k_gemm64(
        const float* __restrict__ in, const float* __restrict__ W,
        const float* __restrict__ b, __half* __restrict__ out, int n) {
    __shared__ float sIn[8 * 64];
    int o = threadIdx.x & 63;
    int nl = threadIdx.x >> 6;   // 0..3
    float wreg[64];
    #pragma unroll
    for (int f = 0; f < 64; f++) wreg[f] = W[f * 64 + o];
    float bias = b[o];
    int base = blockIdx.x * 128;
    for (int k = 0; k < 128; k += 8) {
        __syncthreads();
        if (threadIdx.x < 128) {
            int rr = threadIdx.x >> 4;
            int cc = threadIdx.x & 15;
            int node = base + k + rr;
            float4 v = (node < n) ? __ldg((const float4*)(in + (size_t)node * 64) + cc)
                                  : make_float4(0.f, 0.f, 0.f, 0.f);
            ((float4*)sIn)[threadIdx.x] = v;
        }
        __syncthreads();
        #pragma unroll
        for (int s = 0; s < 2; s++) {
            int r = nl + s * 4;
            int node = base + k + r;
            if (node < n) {
                float acc = bias;
                #pragma unroll
                for (int f = 0; f < 64; f++) acc = fmaf(sIn[r * 64 + f], wreg[f], acc);
                out[(size_t)node * 64 + o] = __float2half_rn(softplus_f(acc));
            }
        }
    }
}

// Layer-3 GEMM fused with the output projection (input fp32 aggregate):
// s1[node] = dinv1[node] * sum_o softplus(gemm_o) * Wout[o].
__global__ __launch_bounds__(256) void k_gemm_wout(
        const float* __restrict__ in, const float* __restrict__ W,
        const float* __restrict__ b, const float* __restrict__ Wout, int n) {
    __shared__ float sIn[8 * 64];
    __shared__ float red[8];
    int o = threadIdx.x & 63;
    int nl = threadIdx.x >> 6;   // 0..3
    float wreg[64];
    #pragma unroll
    for (int f = 0; f < 64; f++) wreg[f] = W[f * 64 + o];
    float bias = b[o];
    float wo = Wout[o];
    int base = blockIdx.x * 128;
    for (int k = 0; k < 128; k += 8) {
        __syncthreads();
        if (threadIdx.x < 128) {
            int rr = threadIdx.x >> 4;
            int cc = threadIdx.x & 15;
            int node = base + k + rr;
            float4 v = (node < n) ? __ldg((const float4*)(in + (size_t)node * 64) + cc)
                                  : make_float4(0.f, 0.f, 0.f, 0.f);
            ((float4*)sIn)[threadIdx.x] = v;
        }
        __syncthreads();
        #pragma unroll
        for (int s = 0; s < 2; s++) {
            int r = nl + s * 4;
            int node = base + k + r;
            float part = 0.f;
            if (node < n) {
                float acc = bias;
                #pragma unroll
                for (int f = 0; f < 64; f++) acc = fmaf(sIn[r * 64 + f], wreg[f], acc);
                part = softplus_f(acc) * wo;
            }
            float ws = warp_sum(part);
            if ((threadIdx.x & 31) == 0) red[threadIdx.x >> 5] = ws;
            __syncthreads();
            if (o == 0 && node < n)
                g_s1[node] = g_dinv1[node] * (red[nl * 2] + red[nl * 2 + 1]);
            __syncthreads();
        }
    }
}

// out[n] = bout + dinv1[n] * (s1[n] + sum_e s1[row[e]])   (warp per node)
__global__ __launch_bounds__(256) void k_out(
        const float* __restrict__ bout, float* __restrict__ out, int n) {
    int w = (blockIdx.x * blockDim.x + threadIdx.x) >> 5;
    if (w >= n) return;
    int lane = threadIdx.x & 31;
    int beg = g_indptr[w], end = g_indptr[w + 1];
    float acc = 0.f;
    for (int e = beg + lane; e < end; e += 32) {
        int r = __ldg(&g_mw[e]).x;
        acc += g_s1[r];
    }
    acc = warp_sum(acc);
    if (lane == 0)
        out[w] = bout[0] + g_dinv1[w] * (acc + g_s1[w]);
}

// ---------------- launch ----------------
extern "C" void kernel_launch(void* const* d_in, const int* in_sizes, int n_in,
                              void* d_out, int out_size) {
    (void)n_in; (void)out_size;
    const void*  edge_idx = d_in[8];
    const float* edge_d   = (const float*)d_in[9];
    const float* x    = (const float*)d_in[1];
    const float* dtr  = (const float*)d_in[2];
    const float* npd  = (const float*)d_in[3];
    const float* kp   = (const float*)d_in[4];
    const float* kpp  = (const float*)d_in[5];
    const float* imin = (const float*)d_in[6];
    const float* imax = (const float*)d_in[7];
    const float* W1 = (const float*)d_in[10];
    const float* b1 = (const float*)d_in[11];
    const float* W2 = (const float*)d_in[12];
    const float* b2 = (const float*)d_in[13];
    const float* W3 = (const float*)d_in[14];
    const float* b3 = (const float*)d_in[15];
    const float* Wout = (const float*)d_in[16];
    const float* bout = (const float*)d_in[17];

    int N = in_sizes[1] / 2;          // x is [N,2]
    int E = in_sizes[9];              // edge_distance is [E]
    if (N > NMAX) N = NMAX;
    if (E > EMAX) E = EMAX;

    __half* pH = nullptr;
    float*  pAgg = nullptr;
    cudaGetSymbolAddress((void**)&pH, g_H);
    cudaGetSymbolAddress((void**)&pAgg, g_Agg);

    const int T = 256;
    int gN  = (N + T - 1) / T;
    int gE  = (E + T - 1) / T;
    int gW  = (N * 32 + T - 1) / T;       // warp-per-node kernels
    int gG  = (N + 127) / 128;            // gemm blocks
    int nb  = (N + 1023) / 1024;          // scan blocks

    k_init_detect<<<gN, T>>>((const int*)edge_idx, N);
    k_convert<<<gE, T>>>(edge_idx, edge_d, E);
    k_bsum<<<nb, 256>>>(N);
    k_fill<<<nb, 256>>>(x, dtr, npd, kp, kpp, imin, imax, N, nb);
    k_place<<<gE, T>>>(edge_idx, edge_d, E);

    // Layer 1: fused aggregate(8) + GEMM(8->64) + softplus -> fp16 table (h1)
    k_agg8_gemm1<<<gW, T>>>(W1, b1, pH, N);

    // Layer 2: gather fp16 h1 -> fp32 aggregate -> GEMM -> fp16 table (h2)
    k_agg64<<<gW, T>>>(pH, pAgg, N);
    k_gemm64<<<gG, 256>>>(pAgg, W2, b2, pH, N);

    // Layer 3: gather fp16 h2 -> fp32 aggregate -> GEMM + output projection
    k_agg64<<<gW, T>>>(pH, pAgg, N);
    k_gemm_wout<<<gG, 256>>>(pAgg, W3, b3, Wout, N);

    // Output conv aggregation with ones-norms
    k_out<<<gW, T>>>(bout, (float*)d_out, N);
}